// round 1
// baseline (speedup 1.0000x reference)
#include <cuda_runtime.h>
#include <math.h>

// Problem constants
constexpr int Bb = 2;
constexpr int Tt = 2048;
constexpr int Cc = 1024;
constexpr int Hh = 16;
constexpr int Dd = 64;    // head dim

// ---------------- scratch (device globals; no cudaMalloc allowed) -------------
__device__ float g_q[(size_t)Bb * Hh * Tt * Dd];   // [B,H,T,D] 16 MB
__device__ float g_k[(size_t)Bb * Hh * Tt * Dd];
__device__ float g_v[(size_t)Bb * Hh * Tt * Dd];
__device__ float g_y[(size_t)Bb * Tt * Cc];        // [B,T,C]   16 MB

// =============================================================================
// Kernel 1: QKV GEMM  (x[4096,1024] @ W[1024,3072] + b) -> scatter to q/k/v
// 128x128 block tile, K-tile 8, 8x8 per-thread micro tile (strided mapping)
// =============================================================================
__global__ __launch_bounds__(256) void qkv_gemm(const float* __restrict__ A,
                                                const float* __restrict__ Bm,
                                                const float* __restrict__ bias) {
    const int K = Cc;
    const int N = 3 * Cc;
    __shared__ float As[8][132];   // padded to dodge store conflicts
    __shared__ float Bs[8][128];

    const int tid = threadIdx.x;
    const int ty = tid >> 4;       // 0..15
    const int tx = tid & 15;       // 0..15
    const int rbase = blockIdx.y * 128;
    const int cbase = blockIdx.x * 128;

    float acc[8][8];
#pragma unroll
    for (int r = 0; r < 8; r++)
#pragma unroll
        for (int c = 0; c < 8; c++) acc[r][c] = 0.f;

    const int arow = tid >> 1;          // 0..127
    const int acol = (tid & 1) * 4;     // 0 or 4
    const int brow = tid >> 5;          // 0..7
    const int bcol = (tid & 31) * 4;    // 0..124

    const float* Aptr = A + (size_t)(rbase + arow) * K + acol;
    const float* Bptr = Bm + (size_t)brow * N + cbase + bcol;

    for (int k0 = 0; k0 < K; k0 += 8) {
        float4 av = *(const float4*)(Aptr + k0);
        float4 bv = *(const float4*)(Bptr + (size_t)k0 * N);
        As[acol + 0][arow] = av.x;
        As[acol + 1][arow] = av.y;
        As[acol + 2][arow] = av.z;
        As[acol + 3][arow] = av.w;
        *(float4*)&Bs[brow][bcol] = bv;
        __syncthreads();
#pragma unroll
        for (int kk = 0; kk < 8; kk++) {
            float a[8], b[8];
#pragma unroll
            for (int r = 0; r < 8; r++) a[r] = As[kk][ty + 16 * r];
#pragma unroll
            for (int c = 0; c < 8; c++) b[c] = Bs[kk][tx + 16 * c];
#pragma unroll
            for (int r = 0; r < 8; r++)
#pragma unroll
                for (int c = 0; c < 8; c++) acc[r][c] += a[r] * b[c];
        }
        __syncthreads();
    }

    // epilogue: add bias, scatter to q/k/v in [B,H,T,D]
#pragma unroll
    for (int r = 0; r < 8; r++) {
        const int m = rbase + ty + 16 * r;
        const int bb = m / Tt;
        const int t = m % Tt;
#pragma unroll
        for (int c = 0; c < 8; c++) {
            const int n = cbase + tx + 16 * c;
            const float v = acc[r][c] + bias[n];
            const int which = n / Cc;      // 0=q 1=k 2=v
            const int cc = n % Cc;
            const int h = cc >> 6;
            const int d = cc & 63;
            const size_t idx = (((size_t)(bb * Hh + h)) * Tt + t) * Dd + d;
            if (which == 0)      g_q[idx] = v;
            else if (which == 1) g_k[idx] = v;
            else                 g_v[idx] = v;
        }
    }
}

// =============================================================================
// Kernel 2: flash attention, fp32 SIMT. BQ=128 query rows per block, BK=64.
// grid = (T/128, B*H), block = 256 (16x16 thread grid, 8x4 regs per thread).
// Causal: only tiles with kbase <= qbase+127 are visited.
// =============================================================================
__global__ __launch_bounds__(256) void attn_kernel() {
    constexpr int BQ = 128, BK = 64, LD = Dd + 1;  // padded row
    extern __shared__ float smem[];
    float* Qs = smem;                 // BQ x LD
    float* Ks = Qs + BQ * LD;         // BK x LD
    float* Vs = Ks + BK * LD;         // BK x LD
    float* Ps = Vs + BK * LD;         // BQ x (BK+1)
    constexpr int LP = BK + 1;

    const int tid = threadIdx.x;
    const int ty = tid >> 4;   // 0..15 (query-row group)
    const int tx = tid & 15;   // 0..15 (col group)
    const int qbase = blockIdx.x * BQ;
    const int bh = blockIdx.y;          // b*H + h

    const float* qptr = g_q + (size_t)bh * Tt * Dd;
    const float* kptr = g_k + (size_t)bh * Tt * Dd;
    const float* vptr = g_v + (size_t)bh * Tt * Dd;

    const float scale = 0.125f;  // 1/sqrt(64)

    // load Q tile (pre-scaled)
    for (int i = tid; i < BQ * Dd / 4; i += 256) {
        const int lin = i * 4;
        const int row = lin >> 6;
        const int col = lin & 63;
        float4 v4 = *(const float4*)(qptr + (size_t)(qbase + row) * Dd + col);
        Qs[row * LD + col + 0] = v4.x * scale;
        Qs[row * LD + col + 1] = v4.y * scale;
        Qs[row * LD + col + 2] = v4.z * scale;
        Qs[row * LD + col + 3] = v4.w * scale;
    }

    float o[8][4];
    float mrow[8], lrow[8];
#pragma unroll
    for (int r = 0; r < 8; r++) {
        mrow[r] = -1e30f;
        lrow[r] = 0.f;
#pragma unroll
        for (int c = 0; c < 4; c++) o[r][c] = 0.f;
    }

    const int nkt = (qbase + BQ) / BK;   // causal tile count
    for (int kt = 0; kt < nkt; kt++) {
        const int kbase = kt * BK;
        __syncthreads();  // prior PV reads done (also orders Q-load stores 1st iter)
        for (int i = tid; i < BK * Dd / 4; i += 256) {
            const int lin = i * 4;
            const int row = lin >> 6;
            const int col = lin & 63;
            float4 k4 = *(const float4*)(kptr + (size_t)(kbase + row) * Dd + col);
            Ks[row * LD + col + 0] = k4.x;
            Ks[row * LD + col + 1] = k4.y;
            Ks[row * LD + col + 2] = k4.z;
            Ks[row * LD + col + 3] = k4.w;
            float4 v4 = *(const float4*)(vptr + (size_t)(kbase + row) * Dd + col);
            Vs[row * LD + col + 0] = v4.x;
            Vs[row * LD + col + 1] = v4.y;
            Vs[row * LD + col + 2] = v4.z;
            Vs[row * LD + col + 3] = v4.w;
        }
        __syncthreads();

        // S = Q @ K^T  (8x4 per thread)
        float s[8][4];
#pragma unroll
        for (int r = 0; r < 8; r++)
#pragma unroll
            for (int c = 0; c < 4; c++) s[r][c] = 0.f;
#pragma unroll 8
        for (int d = 0; d < Dd; d++) {
            float qv[8], kv[4];
#pragma unroll
            for (int r = 0; r < 8; r++) qv[r] = Qs[(ty + 16 * r) * LD + d];
#pragma unroll
            for (int c = 0; c < 4; c++) kv[c] = Ks[(tx + 16 * c) * LD + d];
#pragma unroll
            for (int r = 0; r < 8; r++)
#pragma unroll
                for (int c = 0; c < 4; c++) s[r][c] += qv[r] * kv[c];
        }

        // causal mask (only last two tiles of each q-tile can touch the diagonal)
        if (kbase + BK - 1 > qbase) {
#pragma unroll
            for (int r = 0; r < 8; r++) {
                const int qi = qbase + ty + 16 * r;
#pragma unroll
                for (int c = 0; c < 4; c++) {
                    const int kj = kbase + tx + 16 * c;
                    if (kj > qi) s[r][c] = -1e30f;
                }
            }
        }

        // online softmax (row reduce across tx via 16-lane shuffles)
#pragma unroll
        for (int r = 0; r < 8; r++) {
            float mt = s[r][0];
#pragma unroll
            for (int c = 1; c < 4; c++) mt = fmaxf(mt, s[r][c]);
            mt = fmaxf(mt, __shfl_xor_sync(0xffffffffu, mt, 1));
            mt = fmaxf(mt, __shfl_xor_sync(0xffffffffu, mt, 2));
            mt = fmaxf(mt, __shfl_xor_sync(0xffffffffu, mt, 4));
            mt = fmaxf(mt, __shfl_xor_sync(0xffffffffu, mt, 8));
            const float mn = fmaxf(mrow[r], mt);
            const float alpha = __expf(mrow[r] - mn);
            mrow[r] = mn;
            float ls = 0.f;
#pragma unroll
            for (int c = 0; c < 4; c++) {
                const float p = __expf(s[r][c] - mn);
                s[r][c] = p;
                ls += p;
            }
            ls += __shfl_xor_sync(0xffffffffu, ls, 1);
            ls += __shfl_xor_sync(0xffffffffu, ls, 2);
            ls += __shfl_xor_sync(0xffffffffu, ls, 4);
            ls += __shfl_xor_sync(0xffffffffu, ls, 8);
            lrow[r] = lrow[r] * alpha + ls;
#pragma unroll
            for (int c = 0; c < 4; c++) o[r][c] *= alpha;
        }

        // stage P to shared
#pragma unroll
        for (int r = 0; r < 8; r++)
#pragma unroll
            for (int c = 0; c < 4; c++)
                Ps[(ty + 16 * r) * LP + tx + 16 * c] = s[r][c];
        __syncthreads();

        // O += P @ V
#pragma unroll 8
        for (int j = 0; j < BK; j++) {
            float pv[8], vv[4];
#pragma unroll
            for (int r = 0; r < 8; r++) pv[r] = Ps[(ty + 16 * r) * LP + j];
#pragma unroll
            for (int c = 0; c < 4; c++) vv[c] = Vs[j * LD + tx + 16 * c];
#pragma unroll
            for (int r = 0; r < 8; r++)
#pragma unroll
                for (int c = 0; c < 4; c++) o[r][c] += pv[r] * vv[c];
        }
    }

    // epilogue: normalize and write to y in [B,T,C]
    const int bb = bh / Hh;
    const int h = bh % Hh;
#pragma unroll
    for (int r = 0; r < 8; r++) {
        const float inv = 1.0f / lrow[r];
        const int t = qbase + ty + 16 * r;
#pragma unroll
        for (int c = 0; c < 4; c++) {
            const int d = tx + 16 * c;
            g_y[((size_t)(bb * Tt + t)) * Cc + h * Dd + d] = o[r][c] * inv;
        }
    }
}

// =============================================================================
// Kernel 3: proj GEMM  (y[4096,1024] @ W_proj[1024,1024] + b) -> out
// =============================================================================
__global__ __launch_bounds__(256) void proj_gemm(const float* __restrict__ Bm,
                                                 const float* __restrict__ bias,
                                                 float* __restrict__ out) {
    const int K = Cc;
    const int N = Cc;
    __shared__ float As[8][132];
    __shared__ float Bs[8][128];

    const int tid = threadIdx.x;
    const int ty = tid >> 4;
    const int tx = tid & 15;
    const int rbase = blockIdx.y * 128;
    const int cbase = blockIdx.x * 128;

    float acc[8][8];
#pragma unroll
    for (int r = 0; r < 8; r++)
#pragma unroll
        for (int c = 0; c < 8; c++) acc[r][c] = 0.f;

    const int arow = tid >> 1;
    const int acol = (tid & 1) * 4;
    const int brow = tid >> 5;
    const int bcol = (tid & 31) * 4;

    const float* Aptr = g_y + (size_t)(rbase + arow) * K + acol;
    const float* Bptr = Bm + (size_t)brow * N + cbase + bcol;

    for (int k0 = 0; k0 < K; k0 += 8) {
        float4 av = *(const float4*)(Aptr + k0);
        float4 bv = *(const float4*)(Bptr + (size_t)k0 * N);
        As[acol + 0][arow] = av.x;
        As[acol + 1][arow] = av.y;
        As[acol + 2][arow] = av.z;
        As[acol + 3][arow] = av.w;
        *(float4*)&Bs[brow][bcol] = bv;
        __syncthreads();
#pragma unroll
        for (int kk = 0; kk < 8; kk++) {
            float a[8], b[8];
#pragma unroll
            for (int r = 0; r < 8; r++) a[r] = As[kk][ty + 16 * r];
#pragma unroll
            for (int c = 0; c < 8; c++) b[c] = Bs[kk][tx + 16 * c];
#pragma unroll
            for (int r = 0; r < 8; r++)
#pragma unroll
                for (int c = 0; c < 8; c++) acc[r][c] += a[r] * b[c];
        }
        __syncthreads();
    }

#pragma unroll
    for (int r = 0; r < 8; r++) {
        const int m = rbase + ty + 16 * r;
#pragma unroll
        for (int c = 0; c < 8; c++) {
            const int n = cbase + tx + 16 * c;
            out[(size_t)m * N + n] = acc[r][c] + bias[n];
        }
    }
}

// =============================================================================
extern "C" void kernel_launch(void* const* d_in, const int* in_sizes, int n_in,
                              void* d_out, int out_size) {
    const float* x     = (const float*)d_in[0];
    const float* Wqkv  = (const float*)d_in[1];
    const float* bqkv  = (const float*)d_in[2];
    const float* Wproj = (const float*)d_in[3];
    const float* bproj = (const float*)d_in[4];
    float* out = (float*)d_out;

    // 1) QKV projection
    dim3 g1(3 * Cc / 128, Bb * Tt / 128);   // (24, 32)
    qkv_gemm<<<g1, 256>>>(x, Wqkv, bqkv);

    // 2) flash attention
    const size_t smem_bytes =
        (size_t)(128 * 65 + 64 * 65 + 64 * 65 + 128 * 65) * sizeof(float); // ~99.8 KB
    cudaFuncSetAttribute(attn_kernel, cudaFuncAttributeMaxDynamicSharedMemorySize,
                         (int)smem_bytes);
    attn_kernel<<<dim3(Tt / 128, Bb * Hh), 256, smem_bytes>>>();

    // 3) output projection
    dim3 g3(Cc / 128, Bb * Tt / 128);       // (8, 32)
    proj_gemm<<<g3, 256>>>(Wproj, bproj, out);
}

// round 4
// speedup vs baseline: 2.5234x; 2.5234x over previous
#include <cuda_runtime.h>
#include <math.h>

// Problem constants
constexpr int Bb = 2;
constexpr int Tt = 2048;
constexpr int Cc = 1024;
constexpr int Hh = 16;
constexpr int Dd = 64;

// ---------------- scratch (device globals; no cudaMalloc allowed) ------------
__device__ float g_q[(size_t)Bb * Hh * Tt * Dd];   // [B,H,T,D]
__device__ float g_k[(size_t)Bb * Hh * Tt * Dd];
__device__ float g_v[(size_t)Bb * Hh * Tt * Dd];
__device__ float g_y[(size_t)Bb * Tt * Cc];        // [B,T,C]

// ---------------- tf32 helpers ----------------
__device__ __forceinline__ float cvt_tf32(float x) {
    unsigned r;
    asm("cvt.rna.tf32.f32 %0, %1;" : "=r"(r) : "f"(x));
    return __uint_as_float(r);
}

__device__ __forceinline__ void mma8(float* d, const unsigned* a, const unsigned* b) {
    asm volatile(
        "mma.sync.aligned.m16n8k8.row.col.f32.tf32.tf32.f32 "
        "{%0,%1,%2,%3}, {%4,%5,%6,%7}, {%8,%9}, {%0,%1,%2,%3};"
        : "+f"(d[0]), "+f"(d[1]), "+f"(d[2]), "+f"(d[3])
        : "r"(a[0]), "r"(a[1]), "r"(a[2]), "r"(a[3]), "r"(b[0]), "r"(b[1]));
}

// =============================================================================
// GEMM (tf32 mma): C[M,N] = A[M,K] @ B[K,N] + bias
// mode 0: A = x, scatter to g_q/g_k/g_v   (N = 3C)
// mode 1: A = g_y, write to out           (N = C)
// Block: 256 thr = 8 warps (2x4), tile 128x128x16, warp tile 64x32.
// =============================================================================
__global__ __launch_bounds__(256) void gemm_tf32(const float* __restrict__ A,
                                                 const float* __restrict__ Bm,
                                                 const float* __restrict__ bias,
                                                 float* __restrict__ out,
                                                 int N, int mode) {
    const int K = Cc;
    __shared__ float As[16][132];   // [k][m]
    __shared__ float Bs[16][132];   // [k][n]

    const int tid = threadIdx.x;
    const int warp = tid >> 5;
    const int lane = tid & 31;
    const int wm = warp >> 2;       // 0..1
    const int wn = warp & 3;        // 0..3
    const int rbase = blockIdx.y * 128;
    const int cbase = blockIdx.x * 128;

    const float* Ap = (mode == 1) ? g_y : A;

    float acc[4][4][4];
#pragma unroll
    for (int i = 0; i < 4; i++)
#pragma unroll
        for (int j = 0; j < 4; j++)
#pragma unroll
            for (int v = 0; v < 4; v++) acc[i][j][v] = 0.f;

    // global load mapping
    const int arow = tid >> 1;          // 0..127
    const int acol = (tid & 1) * 8;     // 0 or 8
    const int bkr = tid >> 5;           // 0..7
    const int bc4 = (lane) * 4;         // 0..124

    const float* Aptr = Ap + (size_t)(rbase + arow) * K + acol;
    const float* Bptr = Bm + (size_t)bkr * N + cbase + bc4;

    float4 ra0 = *(const float4*)(Aptr + 0);
    float4 ra1 = *(const float4*)(Aptr + 4);
    float4 rb0 = *(const float4*)(Bptr);
    float4 rb1 = *(const float4*)(Bptr + (size_t)8 * N);

    const int lq = lane >> 2;   // lane/4
    const int lr = lane & 3;    // lane%4

    for (int k0 = 0; k0 < K; k0 += 16) {
        // stage current regs -> SMEM (tf32-rounded)
        As[acol + 0][arow] = cvt_tf32(ra0.x);
        As[acol + 1][arow] = cvt_tf32(ra0.y);
        As[acol + 2][arow] = cvt_tf32(ra0.z);
        As[acol + 3][arow] = cvt_tf32(ra0.w);
        As[acol + 4][arow] = cvt_tf32(ra1.x);
        As[acol + 5][arow] = cvt_tf32(ra1.y);
        As[acol + 6][arow] = cvt_tf32(ra1.z);
        As[acol + 7][arow] = cvt_tf32(ra1.w);
        float4 cb0 = make_float4(cvt_tf32(rb0.x), cvt_tf32(rb0.y), cvt_tf32(rb0.z), cvt_tf32(rb0.w));
        float4 cb1 = make_float4(cvt_tf32(rb1.x), cvt_tf32(rb1.y), cvt_tf32(rb1.z), cvt_tf32(rb1.w));
        *(float4*)&Bs[bkr][bc4] = cb0;
        *(float4*)&Bs[bkr + 8][bc4] = cb1;
        __syncthreads();

        // prefetch next k-tile
        if (k0 + 16 < K) {
            ra0 = *(const float4*)(Aptr + k0 + 16);
            ra1 = *(const float4*)(Aptr + k0 + 20);
            rb0 = *(const float4*)(Bptr + (size_t)(k0 + 16) * N);
            rb1 = *(const float4*)(Bptr + (size_t)(k0 + 24) * N);
        }

#pragma unroll
        for (int kk = 0; kk < 16; kk += 8) {
            unsigned a[4][4], b[4][2];
#pragma unroll
            for (int mi = 0; mi < 4; mi++) {
                const int r0 = wm * 64 + mi * 16 + lq;
                a[mi][0] = __float_as_uint(As[kk + lr][r0]);
                a[mi][1] = __float_as_uint(As[kk + lr][r0 + 8]);
                a[mi][2] = __float_as_uint(As[kk + lr + 4][r0]);
                a[mi][3] = __float_as_uint(As[kk + lr + 4][r0 + 8]);
            }
#pragma unroll
            for (int ni = 0; ni < 4; ni++) {
                const int c0 = wn * 32 + ni * 8 + lq;
                b[ni][0] = __float_as_uint(Bs[kk + lr][c0]);
                b[ni][1] = __float_as_uint(Bs[kk + lr + 4][c0]);
            }
#pragma unroll
            for (int mi = 0; mi < 4; mi++)
#pragma unroll
                for (int ni = 0; ni < 4; ni++) mma8(acc[mi][ni], a[mi], b[ni]);
        }
        __syncthreads();
    }

    // epilogue
#pragma unroll
    for (int mi = 0; mi < 4; mi++) {
#pragma unroll
        for (int ni = 0; ni < 4; ni++) {
#pragma unroll
            for (int v = 0; v < 4; v++) {
                const int row = rbase + wm * 64 + mi * 16 + lq + ((v >= 2) ? 8 : 0);
                const int col = cbase + wn * 32 + ni * 8 + lr * 2 + (v & 1);
                const float val = acc[mi][ni][v] + __ldg(&bias[col]);
                if (mode == 1) {
                    out[(size_t)row * N + col] = val;
                } else {
                    const int bb = row / Tt;
                    const int t = row % Tt;
                    const int which = col / Cc;
                    const int cc = col % Cc;
                    const int h = cc >> 6;
                    const int d = cc & 63;
                    const size_t idx = (((size_t)(bb * Hh + h)) * Tt + t) * Dd + d;
                    if (which == 0)      g_q[idx] = val;
                    else if (which == 1) g_k[idx] = val;
                    else                 g_v[idx] = val;
                }
            }
        }
    }
}

// =============================================================================
// Flash attention, tf32 mma. BQ=128 (16 rows/warp, 8 warps), key tile 64, D=64.
// Each warp owns 16 query rows across ALL 64 keys of a tile -> softmax needs
// only quad shuffles. P staged through per-warp SMEM for the PV mma.
// =============================================================================
__global__ __launch_bounds__(256) void attn_tf32() {
    constexpr int BQ = 128, BKEY = 64, LDA = Dd + 4;   // 68 (pad, 4-aligned)
    extern __shared__ float smem[];
    float* Qs = smem;                          // [128][68]
    float* Ks = Qs + BQ * LDA;                 // [64][68]  (key-major: [key][d])
    float* Vs = Ks + BKEY * LDA;               // [64][68]  ([key][d])
    float* Ps = Vs + BKEY * LDA;               // per-warp [16][68]

    const int tid = threadIdx.x;
    const int warp = tid >> 5;
    const int lane = tid & 31;
    const int lq = lane >> 2;
    const int lr = lane & 3;
    const int qbase = blockIdx.x * BQ;
    const int bh = blockIdx.y;

    const float* qptr = g_q + (size_t)bh * Tt * Dd;
    const float* kptr = g_k + (size_t)bh * Tt * Dd;
    const float* vptr = g_v + (size_t)bh * Tt * Dd;

    float* Pw = Ps + warp * 16 * LDA;

    const float scale = 0.125f;

    // load Q tile (scaled, tf32-rounded)
    for (int i = tid; i < BQ * Dd / 4; i += 256) {
        const int lin = i * 4;
        const int row = lin >> 6;
        const int col = lin & 63;
        float4 v4 = *(const float4*)(qptr + (size_t)(qbase + row) * Dd + col);
        float4 c = make_float4(cvt_tf32(v4.x * scale), cvt_tf32(v4.y * scale),
                               cvt_tf32(v4.z * scale), cvt_tf32(v4.w * scale));
        *(float4*)&Qs[row * LDA + col] = c;
    }

    float o[8][4];
    float m0 = -1e30f, m1 = -1e30f, l0 = 0.f, l1 = 0.f;
#pragma unroll
    for (int j = 0; j < 8; j++)
#pragma unroll
        for (int v = 0; v < 4; v++) o[j][v] = 0.f;

    const int qr0 = warp * 16;                    // warp's row band within tile
    const int qi0 = qbase + qr0 + lq;             // global row of acc slots 0,1
    const int qi1 = qi0 + 8;                      // global row of acc slots 2,3

    const int nkt = (qbase + BQ) / BKEY;
    for (int kt = 0; kt < nkt; kt++) {
        const int kbase = kt * BKEY;
        __syncthreads();   // prior PV done reading Ks/Vs (and orders Q fill @kt=0)
        for (int i = tid; i < BKEY * Dd / 4; i += 256) {
            const int lin = i * 4;
            const int row = lin >> 6;
            const int col = lin & 63;
            float4 k4 = *(const float4*)(kptr + (size_t)(kbase + row) * Dd + col);
            *(float4*)&Ks[row * LDA + col] =
                make_float4(cvt_tf32(k4.x), cvt_tf32(k4.y), cvt_tf32(k4.z), cvt_tf32(k4.w));
            float4 v4 = *(const float4*)(vptr + (size_t)(kbase + row) * Dd + col);
            *(float4*)&Vs[row * LDA + col] =
                make_float4(cvt_tf32(v4.x), cvt_tf32(v4.y), cvt_tf32(v4.z), cvt_tf32(v4.w));
        }
        __syncthreads();

        // ---- S = Q @ K^T : M=16, N=64 keys, K=64 (d) ----
        float s[8][4];
#pragma unroll
        for (int j = 0; j < 8; j++)
#pragma unroll
            for (int v = 0; v < 4; v++) s[j][v] = 0.f;

#pragma unroll
        for (int kk = 0; kk < 8; kk++) {
            const int d0 = kk * 8;
            unsigned a[4];
            a[0] = __float_as_uint(Qs[(qr0 + lq) * LDA + d0 + lr]);
            a[1] = __float_as_uint(Qs[(qr0 + lq + 8) * LDA + d0 + lr]);
            a[2] = __float_as_uint(Qs[(qr0 + lq) * LDA + d0 + lr + 4]);
            a[3] = __float_as_uint(Qs[(qr0 + lq + 8) * LDA + d0 + lr + 4]);
#pragma unroll
            for (int j = 0; j < 8; j++) {
                unsigned b[2];
                b[0] = __float_as_uint(Ks[(j * 8 + lq) * LDA + d0 + lr]);
                b[1] = __float_as_uint(Ks[(j * 8 + lq) * LDA + d0 + lr + 4]);
                mma8(s[j], a, b);
            }
        }

        // causal mask on boundary tiles
        if (kbase + BKEY - 1 > qbase) {
#pragma unroll
            for (int j = 0; j < 8; j++) {
                const int kj = kbase + j * 8 + lr * 2;
                if (kj > qi0)     s[j][0] = -1e30f;
                if (kj + 1 > qi0) s[j][1] = -1e30f;
                if (kj > qi1)     s[j][2] = -1e30f;
                if (kj + 1 > qi1) s[j][3] = -1e30f;
            }
        }

        // ---- online softmax (rows qi0, qi1) ----
        float mt0 = -1e30f, mt1 = -1e30f;
#pragma unroll
        for (int j = 0; j < 8; j++) {
            mt0 = fmaxf(mt0, fmaxf(s[j][0], s[j][1]));
            mt1 = fmaxf(mt1, fmaxf(s[j][2], s[j][3]));
        }
        mt0 = fmaxf(mt0, __shfl_xor_sync(0xffffffffu, mt0, 1));
        mt0 = fmaxf(mt0, __shfl_xor_sync(0xffffffffu, mt0, 2));
        mt1 = fmaxf(mt1, __shfl_xor_sync(0xffffffffu, mt1, 1));
        mt1 = fmaxf(mt1, __shfl_xor_sync(0xffffffffu, mt1, 2));

        const float mn0 = fmaxf(m0, mt0);
        const float mn1 = fmaxf(m1, mt1);
        const float al0 = __expf(m0 - mn0);
        const float al1 = __expf(m1 - mn1);
        m0 = mn0; m1 = mn1;

        float ls0 = 0.f, ls1 = 0.f;
#pragma unroll
        for (int j = 0; j < 8; j++) {
            s[j][0] = __expf(s[j][0] - mn0);
            s[j][1] = __expf(s[j][1] - mn0);
            s[j][2] = __expf(s[j][2] - mn1);
            s[j][3] = __expf(s[j][3] - mn1);
            ls0 += s[j][0] + s[j][1];
            ls1 += s[j][2] + s[j][3];
        }
        ls0 += __shfl_xor_sync(0xffffffffu, ls0, 1);
        ls0 += __shfl_xor_sync(0xffffffffu, ls0, 2);
        ls1 += __shfl_xor_sync(0xffffffffu, ls1, 1);
        ls1 += __shfl_xor_sync(0xffffffffu, ls1, 2);
        l0 = l0 * al0 + ls0;
        l1 = l1 * al1 + ls1;
#pragma unroll
        for (int j = 0; j < 8; j++) {
            o[j][0] *= al0; o[j][1] *= al0;
            o[j][2] *= al1; o[j][3] *= al1;
        }

        // stage P (tf32) to per-warp SMEM
#pragma unroll
        for (int j = 0; j < 8; j++) {
            const int c = j * 8 + lr * 2;
            Pw[lq * LDA + c]       = cvt_tf32(s[j][0]);
            Pw[lq * LDA + c + 1]   = cvt_tf32(s[j][1]);
            Pw[(lq + 8) * LDA + c]     = cvt_tf32(s[j][2]);
            Pw[(lq + 8) * LDA + c + 1] = cvt_tf32(s[j][3]);
        }
        __syncwarp();

        // ---- O += P @ V : M=16, N=64 (d), K=64 keys ----
#pragma unroll
        for (int kk = 0; kk < 8; kk++) {
            const int key0 = kk * 8;
            unsigned a[4];
            a[0] = __float_as_uint(Pw[lq * LDA + key0 + lr]);
            a[1] = __float_as_uint(Pw[(lq + 8) * LDA + key0 + lr]);
            a[2] = __float_as_uint(Pw[lq * LDA + key0 + lr + 4]);
            a[3] = __float_as_uint(Pw[(lq + 8) * LDA + key0 + lr + 4]);
#pragma unroll
            for (int j = 0; j < 8; j++) {
                unsigned b[2];
                b[0] = __float_as_uint(Vs[(key0 + lr) * LDA + j * 8 + lq]);
                b[1] = __float_as_uint(Vs[(key0 + lr + 4) * LDA + j * 8 + lq]);
                mma8(o[j], a, b);
            }
        }
        __syncwarp();   // Pw reads done before next-iter overwrite
    }

    // epilogue: normalize, write to g_y [B,T,C]
    const int bb = bh / Hh;
    const int h = bh % Hh;
    const float inv0 = 1.0f / l0;
    const float inv1 = 1.0f / l1;
    const int t0 = qbase + qr0 + lq;
    const int t1 = t0 + 8;
#pragma unroll
    for (int j = 0; j < 8; j++) {
        const int d = j * 8 + lr * 2;
        float2 w0 = make_float2(o[j][0] * inv0, o[j][1] * inv0);
        float2 w1 = make_float2(o[j][2] * inv1, o[j][3] * inv1);
        *(float2*)&g_y[((size_t)(bb * Tt + t0)) * Cc + h * Dd + d] = w0;
        *(float2*)&g_y[((size_t)(bb * Tt + t1)) * Cc + h * Dd + d] = w1;
    }
}

// =============================================================================
extern "C" void kernel_launch(void* const* d_in, const int* in_sizes, int n_in,
                              void* d_out, int out_size) {
    const float* x     = (const float*)d_in[0];
    const float* Wqkv  = (const float*)d_in[1];
    const float* bqkv  = (const float*)d_in[2];
    const float* Wproj = (const float*)d_in[3];
    const float* bproj = (const float*)d_in[4];
    float* out = (float*)d_out;

    // 1) QKV projection (tf32 mma)
    dim3 g1(3 * Cc / 128, Bb * Tt / 128);   // (24, 32)
    gemm_tf32<<<g1, 256>>>(x, Wqkv, bqkv, nullptr, 3 * Cc, 0);

    // 2) flash attention (tf32 mma)
    const size_t smem_bytes =
        (size_t)(128 * 68 + 64 * 68 + 64 * 68 + 8 * 16 * 68) * sizeof(float); // 104448
    (void)cudaFuncSetAttribute(attn_tf32, cudaFuncAttributeMaxDynamicSharedMemorySize,
                               (int)smem_bytes);
    attn_tf32<<<dim3(Tt / 128, Bb * Hh), 256, smem_bytes>>>();

    // 3) output projection (tf32 mma)
    dim3 g3(Cc / 128, Bb * Tt / 128);       // (8, 32)
    gemm_tf32<<<g3, 256>>>(nullptr, Wproj, bproj, out, Cc, 1);
}

// round 5
// speedup vs baseline: 2.8645x; 1.1352x over previous
#include <cuda_runtime.h>
#include <math.h>

// Problem constants
constexpr int Bb = 2;
constexpr int Tt = 2048;
constexpr int Cc = 1024;
constexpr int Hh = 16;
constexpr int Dd = 64;

// ---------------- scratch (device globals; no cudaMalloc allowed) ------------
__device__ float g_q[(size_t)Bb * Hh * Tt * Dd];   // [B,H,T,D]
__device__ float g_k[(size_t)Bb * Hh * Tt * Dd];
__device__ float g_v[(size_t)Bb * Hh * Tt * Dd];
__device__ float g_y[(size_t)Bb * Tt * Cc];        // [B,T,C]

// ---------------- tf32 helpers ----------------
__device__ __forceinline__ float cvt_tf32(float x) {
    unsigned r;
    asm("cvt.rna.tf32.f32 %0, %1;" : "=r"(r) : "f"(x));
    return __uint_as_float(r);
}

__device__ __forceinline__ void mma8(float* d, const unsigned* a, const unsigned* b) {
    asm volatile(
        "mma.sync.aligned.m16n8k8.row.col.f32.tf32.tf32.f32 "
        "{%0,%1,%2,%3}, {%4,%5,%6,%7}, {%8,%9}, {%0,%1,%2,%3};"
        : "+f"(d[0]), "+f"(d[1]), "+f"(d[2]), "+f"(d[3])
        : "r"(a[0]), "r"(a[1]), "r"(a[2]), "r"(a[3]), "r"(b[0]), "r"(b[1]));
}

// =============================================================================
// GEMM (tf32 mma): C[M,N] = A[M,K] @ B[K,N] + bias
// mode 0: A = x, scatter to g_q/g_k/g_v   (N = 3C)
// mode 1: A = g_y, write to out           (N = C)
// Block: 256 thr = 8 warps (2x4), tile 128x128x16, warp tile 64x32.
// Stride 136 (mod 32 == 8) -> mainloop LDS conflict-free. Double-buffered.
// =============================================================================
constexpr int LDS_ = 136;

__global__ __launch_bounds__(256, 2) void gemm_tf32(const float* __restrict__ A,
                                                    const float* __restrict__ Bm,
                                                    const float* __restrict__ bias,
                                                    float* __restrict__ out,
                                                    int N, int mode) {
    const int K = Cc;
    __shared__ float As[2][16][LDS_];   // [buf][k][m]
    __shared__ float Bs[2][16][LDS_];   // [buf][k][n]

    const int tid = threadIdx.x;
    const int warp = tid >> 5;
    const int lane = tid & 31;
    const int wm = warp >> 2;       // 0..1
    const int wn = warp & 3;        // 0..3
    const int rbase = blockIdx.y * 128;
    const int cbase = blockIdx.x * 128;

    const float* Ap = (mode == 1) ? g_y : A;

    float acc[4][4][4];
#pragma unroll
    for (int i = 0; i < 4; i++)
#pragma unroll
        for (int j = 0; j < 4; j++)
#pragma unroll
            for (int v = 0; v < 4; v++) acc[i][j][v] = 0.f;

    // global load mapping
    const int arow = tid >> 1;          // 0..127
    const int acol = (tid & 1) * 8;     // 0 or 8
    const int bkr = tid >> 5;           // 0..7
    const int bc4 = lane * 4;           // 0..124

    const float* Aptr = Ap + (size_t)(rbase + arow) * K + acol;
    const float* Bptr = Bm + (size_t)bkr * N + cbase + bc4;

    const int lq = lane >> 2;   // lane/4
    const int lr = lane & 3;    // lane%4

    float4 ra0 = *(const float4*)(Aptr + 0);
    float4 ra1 = *(const float4*)(Aptr + 4);
    float4 rb0 = *(const float4*)(Bptr);
    float4 rb1 = *(const float4*)(Bptr + (size_t)8 * N);

    // stage k-tile 0 into buffer 0
    {
        As[0][acol + 0][arow] = cvt_tf32(ra0.x);
        As[0][acol + 1][arow] = cvt_tf32(ra0.y);
        As[0][acol + 2][arow] = cvt_tf32(ra0.z);
        As[0][acol + 3][arow] = cvt_tf32(ra0.w);
        As[0][acol + 4][arow] = cvt_tf32(ra1.x);
        As[0][acol + 5][arow] = cvt_tf32(ra1.y);
        As[0][acol + 6][arow] = cvt_tf32(ra1.z);
        As[0][acol + 7][arow] = cvt_tf32(ra1.w);
        float4 cb0 = make_float4(cvt_tf32(rb0.x), cvt_tf32(rb0.y), cvt_tf32(rb0.z), cvt_tf32(rb0.w));
        float4 cb1 = make_float4(cvt_tf32(rb1.x), cvt_tf32(rb1.y), cvt_tf32(rb1.z), cvt_tf32(rb1.w));
        *(float4*)&Bs[0][bkr][bc4] = cb0;
        *(float4*)&Bs[0][bkr + 8][bc4] = cb1;
    }
    __syncthreads();

    int buf = 0;
    for (int k0 = 0; k0 < K; k0 += 16) {
        const bool more = (k0 + 16 < K);
        if (more) {
            ra0 = *(const float4*)(Aptr + k0 + 16);
            ra1 = *(const float4*)(Aptr + k0 + 20);
            rb0 = *(const float4*)(Bptr + (size_t)(k0 + 16) * N);
            rb1 = *(const float4*)(Bptr + (size_t)(k0 + 24) * N);
        }

#pragma unroll
        for (int kk = 0; kk < 16; kk += 8) {
            unsigned a[4][4], b[4][2];
#pragma unroll
            for (int mi = 0; mi < 4; mi++) {
                const int r0 = wm * 64 + mi * 16 + lq;
                a[mi][0] = __float_as_uint(As[buf][kk + lr][r0]);
                a[mi][1] = __float_as_uint(As[buf][kk + lr][r0 + 8]);
                a[mi][2] = __float_as_uint(As[buf][kk + lr + 4][r0]);
                a[mi][3] = __float_as_uint(As[buf][kk + lr + 4][r0 + 8]);
            }
#pragma unroll
            for (int ni = 0; ni < 4; ni++) {
                const int c0 = wn * 32 + ni * 8 + lq;
                b[ni][0] = __float_as_uint(Bs[buf][kk + lr][c0]);
                b[ni][1] = __float_as_uint(Bs[buf][kk + lr + 4][c0]);
            }
#pragma unroll
            for (int mi = 0; mi < 4; mi++)
#pragma unroll
                for (int ni = 0; ni < 4; ni++) mma8(acc[mi][ni], a[mi], b[ni]);
        }

        if (more) {
            const int nb = buf ^ 1;
            As[nb][acol + 0][arow] = cvt_tf32(ra0.x);
            As[nb][acol + 1][arow] = cvt_tf32(ra0.y);
            As[nb][acol + 2][arow] = cvt_tf32(ra0.z);
            As[nb][acol + 3][arow] = cvt_tf32(ra0.w);
            As[nb][acol + 4][arow] = cvt_tf32(ra1.x);
            As[nb][acol + 5][arow] = cvt_tf32(ra1.y);
            As[nb][acol + 6][arow] = cvt_tf32(ra1.z);
            As[nb][acol + 7][arow] = cvt_tf32(ra1.w);
            float4 cb0 = make_float4(cvt_tf32(rb0.x), cvt_tf32(rb0.y), cvt_tf32(rb0.z), cvt_tf32(rb0.w));
            float4 cb1 = make_float4(cvt_tf32(rb1.x), cvt_tf32(rb1.y), cvt_tf32(rb1.z), cvt_tf32(rb1.w));
            *(float4*)&Bs[nb][bkr][bc4] = cb0;
            *(float4*)&Bs[nb][bkr + 8][bc4] = cb1;
        }
        __syncthreads();
        buf ^= 1;
    }

    // epilogue
#pragma unroll
    for (int mi = 0; mi < 4; mi++) {
#pragma unroll
        for (int ni = 0; ni < 4; ni++) {
#pragma unroll
            for (int v = 0; v < 4; v++) {
                const int row = rbase + wm * 64 + mi * 16 + lq + ((v >= 2) ? 8 : 0);
                const int col = cbase + wn * 32 + ni * 8 + lr * 2 + (v & 1);
                const float val = acc[mi][ni][v] + __ldg(&bias[col]);
                if (mode == 1) {
                    out[(size_t)row * N + col] = val;
                } else {
                    const int bb = row / Tt;
                    const int t = row % Tt;
                    const int which = col / Cc;
                    const int cc = col % Cc;
                    const int h = cc >> 6;
                    const int d = cc & 63;
                    const size_t idx = (((size_t)(bb * Hh + h)) * Tt + t) * Dd + d;
                    if (which == 0)      g_q[idx] = val;
                    else if (which == 1) g_k[idx] = val;
                    else                 g_v[idx] = val;
                }
            }
        }
    }
}

// =============================================================================
// Flash attention, tf32 mma. BQ=128 (16 rows/warp, 8 warps), key tile 64, D=64.
// (unchanged from the passing round-4 version)
// =============================================================================
__global__ __launch_bounds__(256) void attn_tf32() {
    constexpr int BQ = 128, BKEY = 64, LDA = Dd + 4;   // 68 (pad, 4-aligned)
    extern __shared__ float smem[];
    float* Qs = smem;                          // [128][68]
    float* Ks = Qs + BQ * LDA;                 // [64][68]  (key-major: [key][d])
    float* Vs = Ks + BKEY * LDA;               // [64][68]  ([key][d])
    float* Ps = Vs + BKEY * LDA;               // per-warp [16][68]

    const int tid = threadIdx.x;
    const int warp = tid >> 5;
    const int lane = tid & 31;
    const int lq = lane >> 2;
    const int lr = lane & 3;
    const int qbase = blockIdx.x * BQ;
    const int bh = blockIdx.y;

    const float* qptr = g_q + (size_t)bh * Tt * Dd;
    const float* kptr = g_k + (size_t)bh * Tt * Dd;
    const float* vptr = g_v + (size_t)bh * Tt * Dd;

    float* Pw = Ps + warp * 16 * LDA;

    const float scale = 0.125f;

    // load Q tile (scaled, tf32-rounded)
    for (int i = tid; i < BQ * Dd / 4; i += 256) {
        const int lin = i * 4;
        const int row = lin >> 6;
        const int col = lin & 63;
        float4 v4 = *(const float4*)(qptr + (size_t)(qbase + row) * Dd + col);
        float4 c = make_float4(cvt_tf32(v4.x * scale), cvt_tf32(v4.y * scale),
                               cvt_tf32(v4.z * scale), cvt_tf32(v4.w * scale));
        *(float4*)&Qs[row * LDA + col] = c;
    }

    float o[8][4];
    float m0 = -1e30f, m1 = -1e30f, l0 = 0.f, l1 = 0.f;
#pragma unroll
    for (int j = 0; j < 8; j++)
#pragma unroll
        for (int v = 0; v < 4; v++) o[j][v] = 0.f;

    const int qr0 = warp * 16;                    // warp's row band within tile
    const int qi0 = qbase + qr0 + lq;             // global row of acc slots 0,1
    const int qi1 = qi0 + 8;                      // global row of acc slots 2,3

    const int nkt = (qbase + BQ) / BKEY;
    for (int kt = 0; kt < nkt; kt++) {
        const int kbase = kt * BKEY;
        __syncthreads();   // prior PV done reading Ks/Vs (and orders Q fill @kt=0)
        for (int i = tid; i < BKEY * Dd / 4; i += 256) {
            const int lin = i * 4;
            const int row = lin >> 6;
            const int col = lin & 63;
            float4 k4 = *(const float4*)(kptr + (size_t)(kbase + row) * Dd + col);
            *(float4*)&Ks[row * LDA + col] =
                make_float4(cvt_tf32(k4.x), cvt_tf32(k4.y), cvt_tf32(k4.z), cvt_tf32(k4.w));
            float4 v4 = *(const float4*)(vptr + (size_t)(kbase + row) * Dd + col);
            *(float4*)&Vs[row * LDA + col] =
                make_float4(cvt_tf32(v4.x), cvt_tf32(v4.y), cvt_tf32(v4.z), cvt_tf32(v4.w));
        }
        __syncthreads();

        // ---- S = Q @ K^T : M=16, N=64 keys, K=64 (d) ----
        float s[8][4];
#pragma unroll
        for (int j = 0; j < 8; j++)
#pragma unroll
            for (int v = 0; v < 4; v++) s[j][v] = 0.f;

#pragma unroll
        for (int kk = 0; kk < 8; kk++) {
            const int d0 = kk * 8;
            unsigned a[4];
            a[0] = __float_as_uint(Qs[(qr0 + lq) * LDA + d0 + lr]);
            a[1] = __float_as_uint(Qs[(qr0 + lq + 8) * LDA + d0 + lr]);
            a[2] = __float_as_uint(Qs[(qr0 + lq) * LDA + d0 + lr + 4]);
            a[3] = __float_as_uint(Qs[(qr0 + lq + 8) * LDA + d0 + lr + 4]);
#pragma unroll
            for (int j = 0; j < 8; j++) {
                unsigned b[2];
                b[0] = __float_as_uint(Ks[(j * 8 + lq) * LDA + d0 + lr]);
                b[1] = __float_as_uint(Ks[(j * 8 + lq) * LDA + d0 + lr + 4]);
                mma8(s[j], a, b);
            }
        }

        // causal mask on boundary tiles
        if (kbase + BKEY - 1 > qbase) {
#pragma unroll
            for (int j = 0; j < 8; j++) {
                const int kj = kbase + j * 8 + lr * 2;
                if (kj > qi0)     s[j][0] = -1e30f;
                if (kj + 1 > qi0) s[j][1] = -1e30f;
                if (kj > qi1)     s[j][2] = -1e30f;
                if (kj + 1 > qi1) s[j][3] = -1e30f;
            }
        }

        // ---- online softmax (rows qi0, qi1) ----
        float mt0 = -1e30f, mt1 = -1e30f;
#pragma unroll
        for (int j = 0; j < 8; j++) {
            mt0 = fmaxf(mt0, fmaxf(s[j][0], s[j][1]));
            mt1 = fmaxf(mt1, fmaxf(s[j][2], s[j][3]));
        }
        mt0 = fmaxf(mt0, __shfl_xor_sync(0xffffffffu, mt0, 1));
        mt0 = fmaxf(mt0, __shfl_xor_sync(0xffffffffu, mt0, 2));
        mt1 = fmaxf(mt1, __shfl_xor_sync(0xffffffffu, mt1, 1));
        mt1 = fmaxf(mt1, __shfl_xor_sync(0xffffffffu, mt1, 2));

        const float mn0 = fmaxf(m0, mt0);
        const float mn1 = fmaxf(m1, mt1);
        const float al0 = __expf(m0 - mn0);
        const float al1 = __expf(m1 - mn1);
        m0 = mn0; m1 = mn1;

        float ls0 = 0.f, ls1 = 0.f;
#pragma unroll
        for (int j = 0; j < 8; j++) {
            s[j][0] = __expf(s[j][0] - mn0);
            s[j][1] = __expf(s[j][1] - mn0);
            s[j][2] = __expf(s[j][2] - mn1);
            s[j][3] = __expf(s[j][3] - mn1);
            ls0 += s[j][0] + s[j][1];
            ls1 += s[j][2] + s[j][3];
        }
        ls0 += __shfl_xor_sync(0xffffffffu, ls0, 1);
        ls0 += __shfl_xor_sync(0xffffffffu, ls0, 2);
        ls1 += __shfl_xor_sync(0xffffffffu, ls1, 1);
        ls1 += __shfl_xor_sync(0xffffffffu, ls1, 2);
        l0 = l0 * al0 + ls0;
        l1 = l1 * al1 + ls1;
#pragma unroll
        for (int j = 0; j < 8; j++) {
            o[j][0] *= al0; o[j][1] *= al0;
            o[j][2] *= al1; o[j][3] *= al1;
        }

        // stage P (tf32) to per-warp SMEM
#pragma unroll
        for (int j = 0; j < 8; j++) {
            const int c = j * 8 + lr * 2;
            Pw[lq * LDA + c]       = cvt_tf32(s[j][0]);
            Pw[lq * LDA + c + 1]   = cvt_tf32(s[j][1]);
            Pw[(lq + 8) * LDA + c]     = cvt_tf32(s[j][2]);
            Pw[(lq + 8) * LDA + c + 1] = cvt_tf32(s[j][3]);
        }
        __syncwarp();

        // ---- O += P @ V : M=16, N=64 (d), K=64 keys ----
#pragma unroll
        for (int kk = 0; kk < 8; kk++) {
            const int key0 = kk * 8;
            unsigned a[4];
            a[0] = __float_as_uint(Pw[lq * LDA + key0 + lr]);
            a[1] = __float_as_uint(Pw[(lq + 8) * LDA + key0 + lr]);
            a[2] = __float_as_uint(Pw[lq * LDA + key0 + lr + 4]);
            a[3] = __float_as_uint(Pw[(lq + 8) * LDA + key0 + lr + 4]);
#pragma unroll
            for (int j = 0; j < 8; j++) {
                unsigned b[2];
                b[0] = __float_as_uint(Vs[(key0 + lr) * LDA + j * 8 + lq]);
                b[1] = __float_as_uint(Vs[(key0 + lr + 4) * LDA + j * 8 + lq]);
                mma8(o[j], a, b);
            }
        }
        __syncwarp();   // Pw reads done before next-iter overwrite
    }

    // epilogue: normalize, write to g_y [B,T,C]
    const int bb = bh / Hh;
    const int h = bh % Hh;
    const float inv0 = 1.0f / l0;
    const float inv1 = 1.0f / l1;
    const int t0 = qbase + qr0 + lq;
    const int t1 = t0 + 8;
#pragma unroll
    for (int j = 0; j < 8; j++) {
        const int d = j * 8 + lr * 2;
        float2 w0 = make_float2(o[j][0] * inv0, o[j][1] * inv0);
        float2 w1 = make_float2(o[j][2] * inv1, o[j][3] * inv1);
        *(float2*)&g_y[((size_t)(bb * Tt + t0)) * Cc + h * Dd + d] = w0;
        *(float2*)&g_y[((size_t)(bb * Tt + t1)) * Cc + h * Dd + d] = w1;
    }
}

// =============================================================================
extern "C" void kernel_launch(void* const* d_in, const int* in_sizes, int n_in,
                              void* d_out, int out_size) {
    const float* x     = (const float*)d_in[0];
    const float* Wqkv  = (const float*)d_in[1];
    const float* bqkv  = (const float*)d_in[2];
    const float* Wproj = (const float*)d_in[3];
    const float* bproj = (const float*)d_in[4];
    float* out = (float*)d_out;

    // 1) QKV projection (tf32 mma)
    dim3 g1(3 * Cc / 128, Bb * Tt / 128);   // (24, 32)
    gemm_tf32<<<g1, 256>>>(x, Wqkv, bqkv, nullptr, 3 * Cc, 0);

    // 2) flash attention (tf32 mma)
    const size_t smem_bytes =
        (size_t)(128 * 68 + 64 * 68 + 64 * 68 + 8 * 16 * 68) * sizeof(float); // 104448
    (void)cudaFuncSetAttribute(attn_tf32, cudaFuncAttributeMaxDynamicSharedMemorySize,
                               (int)smem_bytes);
    attn_tf32<<<dim3(Tt / 128, Bb * Hh), 256, smem_bytes>>>();

    // 3) output projection (tf32 mma)
    dim3 g3(Cc / 128, Bb * Tt / 128);       // (8, 32)
    gemm_tf32<<<g3, 256>>>(nullptr, Wproj, bproj, out, Cc, 1);
}

// round 7
// speedup vs baseline: 2.9818x; 1.0409x over previous
#include <cuda_runtime.h>
#include <math.h>

// Problem constants
constexpr int Bb = 2;
constexpr int Tt = 2048;
constexpr int Cc = 1024;
constexpr int Hh = 16;
constexpr int Dd = 64;

// ---------------- scratch (device globals; no cudaMalloc allowed) ------------
__device__ float g_q[(size_t)Bb * Hh * Tt * Dd];   // [B,H,T,D]
__device__ float g_k[(size_t)Bb * Hh * Tt * Dd];
__device__ float g_v[(size_t)Bb * Hh * Tt * Dd];
__device__ float g_y[(size_t)Bb * Tt * Cc];        // [B,T,C]

// ---------------- tf32 helpers ----------------
__device__ __forceinline__ float cvt_tf32(float x) {
    unsigned r;
    asm("cvt.rna.tf32.f32 %0, %1;" : "=r"(r) : "f"(x));
    return __uint_as_float(r);
}

__device__ __forceinline__ void mma8(float* d, const unsigned* a, const unsigned* b) {
    asm volatile(
        "mma.sync.aligned.m16n8k8.row.col.f32.tf32.tf32.f32 "
        "{%0,%1,%2,%3}, {%4,%5,%6,%7}, {%8,%9}, {%0,%1,%2,%3};"
        : "+f"(d[0]), "+f"(d[1]), "+f"(d[2]), "+f"(d[3])
        : "r"(a[0]), "r"(a[1]), "r"(a[2]), "r"(a[3]), "r"(b[0]), "r"(b[1]));
}

// =============================================================================
// GEMM (tf32 mma): C[M,N] = A[M,1024] @ B[1024,N] + bias
// Block tile 128x256, k-tile 16, 8 warps in 2x4 -> warp tile 64x64.
// LDS/mma = 1.0 (was 1.5 at 64x32). A stride 136, B stride 264 (both mod32=8,
// conflict-free fragment loads). Double-buffered SMEM (51200 B dynamic).
// mode 0: A = x, scatter to g_q/g_k/g_v (N=3072). mode 1: A = g_y -> out (N=1024).
// =============================================================================
constexpr int LA = 136;            // A row stride (floats)
constexpr int LB = 264;            // B row stride (floats)
constexpr int SM_GEMM_BYTES = (2 * 16 * LA + 2 * 16 * LB) * 4;   // 51200

__global__ __launch_bounds__(256) void gemm_tf32(const float* __restrict__ A,
                                                 const float* __restrict__ Bm,
                                                 const float* __restrict__ bias,
                                                 float* __restrict__ out,
                                                 int N, int mode) {
    const int K = Cc;
    extern __shared__ float smg[];
    float* As = smg;                     // [2][16][LA]
    float* Bs = smg + 2 * 16 * LA;       // [2][16][LB]

    const int tid = threadIdx.x;
    const int warp = tid >> 5;
    const int lane = tid & 31;
    const int wm = warp >> 2;       // 0..1  (m: 64 each)
    const int wn = warp & 3;        // 0..3  (n: 64 each)
    const int rbase = blockIdx.y * 128;
    const int cbase = blockIdx.x * 256;

    const float* Ap = (mode == 1) ? g_y : A;

    float acc[4][8][4];
#pragma unroll
    for (int i = 0; i < 4; i++)
#pragma unroll
        for (int j = 0; j < 8; j++)
#pragma unroll
            for (int v = 0; v < 4; v++) acc[i][j][v] = 0.f;

    // global load mapping
    const int arow = tid >> 1;          // 0..127
    const int acol = (tid & 1) * 8;     // 0 or 8
    const int brk = tid >> 6;           // 0..3 (k row base)
    const int bc4 = (tid & 63) * 4;     // 0..252

    const float* Aptr = Ap + (size_t)(rbase + arow) * K + acol;
    const float* Bptr = Bm + (size_t)brk * N + cbase + bc4;

    const int lq = lane >> 2;   // lane/4
    const int lr = lane & 3;    // lane%4

    float4 ra0 = *(const float4*)(Aptr + 0);
    float4 ra1 = *(const float4*)(Aptr + 4);
    float4 rb[4];
#pragma unroll
    for (int i = 0; i < 4; i++)
        rb[i] = *(const float4*)(Bptr + (size_t)(4 * i) * N);

    // stage k-tile 0 into buffer 0
    {
        float* A0 = As;
        A0[(acol + 0) * LA + arow] = cvt_tf32(ra0.x);
        A0[(acol + 1) * LA + arow] = cvt_tf32(ra0.y);
        A0[(acol + 2) * LA + arow] = cvt_tf32(ra0.z);
        A0[(acol + 3) * LA + arow] = cvt_tf32(ra0.w);
        A0[(acol + 4) * LA + arow] = cvt_tf32(ra1.x);
        A0[(acol + 5) * LA + arow] = cvt_tf32(ra1.y);
        A0[(acol + 6) * LA + arow] = cvt_tf32(ra1.z);
        A0[(acol + 7) * LA + arow] = cvt_tf32(ra1.w);
#pragma unroll
        for (int i = 0; i < 4; i++) {
            float4 c = make_float4(cvt_tf32(rb[i].x), cvt_tf32(rb[i].y),
                                   cvt_tf32(rb[i].z), cvt_tf32(rb[i].w));
            *(float4*)&Bs[(brk + 4 * i) * LB + bc4] = c;
        }
    }
    __syncthreads();

    int buf = 0;
    for (int k0 = 0; k0 < K; k0 += 16) {
        const bool more = (k0 + 16 < K);
        if (more) {
            ra0 = *(const float4*)(Aptr + k0 + 16);
            ra1 = *(const float4*)(Aptr + k0 + 20);
#pragma unroll
            for (int i = 0; i < 4; i++)
                rb[i] = *(const float4*)(Bptr + (size_t)(k0 + 16 + 4 * i) * N);
        }

        const float* Ab = As + buf * 16 * LA;
        const float* Bb = Bs + buf * 16 * LB;
#pragma unroll
        for (int kk = 0; kk < 16; kk += 8) {
            unsigned a[4][4], b[8][2];
#pragma unroll
            for (int mi = 0; mi < 4; mi++) {
                const int r0 = wm * 64 + mi * 16 + lq;
                a[mi][0] = __float_as_uint(Ab[(kk + lr) * LA + r0]);
                a[mi][1] = __float_as_uint(Ab[(kk + lr) * LA + r0 + 8]);
                a[mi][2] = __float_as_uint(Ab[(kk + lr + 4) * LA + r0]);
                a[mi][3] = __float_as_uint(Ab[(kk + lr + 4) * LA + r0 + 8]);
            }
#pragma unroll
            for (int ni = 0; ni < 8; ni++) {
                const int c0 = wn * 64 + ni * 8 + lq;
                b[ni][0] = __float_as_uint(Bb[(kk + lr) * LB + c0]);
                b[ni][1] = __float_as_uint(Bb[(kk + lr + 4) * LB + c0]);
            }
#pragma unroll
            for (int mi = 0; mi < 4; mi++)
#pragma unroll
                for (int ni = 0; ni < 8; ni++) mma8(acc[mi][ni], a[mi], b[ni]);
        }

        if (more) {
            const int nb = buf ^ 1;
            float* An = As + nb * 16 * LA;
            float* Bn = Bs + nb * 16 * LB;
            An[(acol + 0) * LA + arow] = cvt_tf32(ra0.x);
            An[(acol + 1) * LA + arow] = cvt_tf32(ra0.y);
            An[(acol + 2) * LA + arow] = cvt_tf32(ra0.z);
            An[(acol + 3) * LA + arow] = cvt_tf32(ra0.w);
            An[(acol + 4) * LA + arow] = cvt_tf32(ra1.x);
            An[(acol + 5) * LA + arow] = cvt_tf32(ra1.y);
            An[(acol + 6) * LA + arow] = cvt_tf32(ra1.z);
            An[(acol + 7) * LA + arow] = cvt_tf32(ra1.w);
#pragma unroll
            for (int i = 0; i < 4; i++) {
                float4 c = make_float4(cvt_tf32(rb[i].x), cvt_tf32(rb[i].y),
                                       cvt_tf32(rb[i].z), cvt_tf32(rb[i].w));
                *(float4*)&Bn[(brk + 4 * i) * LB + bc4] = c;
            }
        }
        __syncthreads();
        buf ^= 1;
    }

    // epilogue
#pragma unroll
    for (int mi = 0; mi < 4; mi++) {
#pragma unroll
        for (int ni = 0; ni < 8; ni++) {
#pragma unroll
            for (int v = 0; v < 4; v++) {
                const int row = rbase + wm * 64 + mi * 16 + lq + ((v >= 2) ? 8 : 0);
                const int col = cbase + wn * 64 + ni * 8 + lr * 2 + (v & 1);
                const float val = acc[mi][ni][v] + __ldg(&bias[col]);
                if (mode == 1) {
                    out[(size_t)row * N + col] = val;
                } else {
                    const int bb = row / Tt;
                    const int t = row % Tt;
                    const int which = col / Cc;
                    const int cc = col % Cc;
                    const int h = cc >> 6;
                    const int d = cc & 63;
                    const size_t idx = (((size_t)(bb * Hh + h)) * Tt + t) * Dd + d;
                    if (which == 0)      g_q[idx] = val;
                    else if (which == 1) g_k[idx] = val;
                    else                 g_v[idx] = val;
                }
            }
        }
    }
}

// =============================================================================
// Flash attention, tf32 mma (unchanged passing round-5 version).
// =============================================================================
__global__ __launch_bounds__(256) void attn_tf32() {
    constexpr int BQ = 128, BKEY = 64, LDA = Dd + 4;
    extern __shared__ float smem[];
    float* Qs = smem;
    float* Ks = Qs + BQ * LDA;
    float* Vs = Ks + BKEY * LDA;
    float* Ps = Vs + BKEY * LDA;

    const int tid = threadIdx.x;
    const int warp = tid >> 5;
    const int lane = tid & 31;
    const int lq = lane >> 2;
    const int lr = lane & 3;
    const int qbase = blockIdx.x * BQ;
    const int bh = blockIdx.y;

    const float* qptr = g_q + (size_t)bh * Tt * Dd;
    const float* kptr = g_k + (size_t)bh * Tt * Dd;
    const float* vptr = g_v + (size_t)bh * Tt * Dd;

    float* Pw = Ps + warp * 16 * LDA;
    const float scale = 0.125f;

    for (int i = tid; i < BQ * Dd / 4; i += 256) {
        const int lin = i * 4;
        const int row = lin >> 6;
        const int col = lin & 63;
        float4 v4 = *(const float4*)(qptr + (size_t)(qbase + row) * Dd + col);
        float4 c = make_float4(cvt_tf32(v4.x * scale), cvt_tf32(v4.y * scale),
                               cvt_tf32(v4.z * scale), cvt_tf32(v4.w * scale));
        *(float4*)&Qs[row * LDA + col] = c;
    }

    float o[8][4];
    float m0 = -1e30f, m1 = -1e30f, l0 = 0.f, l1 = 0.f;
#pragma unroll
    for (int j = 0; j < 8; j++)
#pragma unroll
        for (int v = 0; v < 4; v++) o[j][v] = 0.f;

    const int qr0 = warp * 16;
    const int qi0 = qbase + qr0 + lq;
    const int qi1 = qi0 + 8;

    const int nkt = (qbase + BQ) / BKEY;
    for (int kt = 0; kt < nkt; kt++) {
        const int kbase = kt * BKEY;
        __syncthreads();
        for (int i = tid; i < BKEY * Dd / 4; i += 256) {
            const int lin = i * 4;
            const int row = lin >> 6;
            const int col = lin & 63;
            float4 k4 = *(const float4*)(kptr + (size_t)(kbase + row) * Dd + col);
            *(float4*)&Ks[row * LDA + col] =
                make_float4(cvt_tf32(k4.x), cvt_tf32(k4.y), cvt_tf32(k4.z), cvt_tf32(k4.w));
            float4 v4 = *(const float4*)(vptr + (size_t)(kbase + row) * Dd + col);
            *(float4*)&Vs[row * LDA + col] =
                make_float4(cvt_tf32(v4.x), cvt_tf32(v4.y), cvt_tf32(v4.z), cvt_tf32(v4.w));
        }
        __syncthreads();

        float s[8][4];
#pragma unroll
        for (int j = 0; j < 8; j++)
#pragma unroll
            for (int v = 0; v < 4; v++) s[j][v] = 0.f;

#pragma unroll
        for (int kk = 0; kk < 8; kk++) {
            const int d0 = kk * 8;
            unsigned a[4];
            a[0] = __float_as_uint(Qs[(qr0 + lq) * LDA + d0 + lr]);
            a[1] = __float_as_uint(Qs[(qr0 + lq + 8) * LDA + d0 + lr]);
            a[2] = __float_as_uint(Qs[(qr0 + lq) * LDA + d0 + lr + 4]);
            a[3] = __float_as_uint(Qs[(qr0 + lq + 8) * LDA + d0 + lr + 4]);
#pragma unroll
            for (int j = 0; j < 8; j++) {
                unsigned b[2];
                b[0] = __float_as_uint(Ks[(j * 8 + lq) * LDA + d0 + lr]);
                b[1] = __float_as_uint(Ks[(j * 8 + lq) * LDA + d0 + lr + 4]);
                mma8(s[j], a, b);
            }
        }

        if (kbase + BKEY - 1 > qbase) {
#pragma unroll
            for (int j = 0; j < 8; j++) {
                const int kj = kbase + j * 8 + lr * 2;
                if (kj > qi0)     s[j][0] = -1e30f;
                if (kj + 1 > qi0) s[j][1] = -1e30f;
                if (kj > qi1)     s[j][2] = -1e30f;
                if (kj + 1 > qi1) s[j][3] = -1e30f;
            }
        }

        float mt0 = -1e30f, mt1 = -1e30f;
#pragma unroll
        for (int j = 0; j < 8; j++) {
            mt0 = fmaxf(mt0, fmaxf(s[j][0], s[j][1]));
            mt1 = fmaxf(mt1, fmaxf(s[j][2], s[j][3]));
        }
        mt0 = fmaxf(mt0, __shfl_xor_sync(0xffffffffu, mt0, 1));
        mt0 = fmaxf(mt0, __shfl_xor_sync(0xffffffffu, mt0, 2));
        mt1 = fmaxf(mt1, __shfl_xor_sync(0xffffffffu, mt1, 1));
        mt1 = fmaxf(mt1, __shfl_xor_sync(0xffffffffu, mt1, 2));

        const float mn0 = fmaxf(m0, mt0);
        const float mn1 = fmaxf(m1, mt1);
        const float al0 = __expf(m0 - mn0);
        const float al1 = __expf(m1 - mn1);
        m0 = mn0; m1 = mn1;

        float ls0 = 0.f, ls1 = 0.f;
#pragma unroll
        for (int j = 0; j < 8; j++) {
            s[j][0] = __expf(s[j][0] - mn0);
            s[j][1] = __expf(s[j][1] - mn0);
            s[j][2] = __expf(s[j][2] - mn1);
            s[j][3] = __expf(s[j][3] - mn1);
            ls0 += s[j][0] + s[j][1];
            ls1 += s[j][2] + s[j][3];
        }
        ls0 += __shfl_xor_sync(0xffffffffu, ls0, 1);
        ls0 += __shfl_xor_sync(0xffffffffu, ls0, 2);
        ls1 += __shfl_xor_sync(0xffffffffu, ls1, 1);
        ls1 += __shfl_xor_sync(0xffffffffu, ls1, 2);
        l0 = l0 * al0 + ls0;
        l1 = l1 * al1 + ls1;
#pragma unroll
        for (int j = 0; j < 8; j++) {
            o[j][0] *= al0; o[j][1] *= al0;
            o[j][2] *= al1; o[j][3] *= al1;
        }

#pragma unroll
        for (int j = 0; j < 8; j++) {
            const int c = j * 8 + lr * 2;
            Pw[lq * LDA + c]           = cvt_tf32(s[j][0]);
            Pw[lq * LDA + c + 1]       = cvt_tf32(s[j][1]);
            Pw[(lq + 8) * LDA + c]     = cvt_tf32(s[j][2]);
            Pw[(lq + 8) * LDA + c + 1] = cvt_tf32(s[j][3]);
        }
        __syncwarp();

#pragma unroll
        for (int kk = 0; kk < 8; kk++) {
            const int key0 = kk * 8;
            unsigned a[4];
            a[0] = __float_as_uint(Pw[lq * LDA + key0 + lr]);
            a[1] = __float_as_uint(Pw[(lq + 8) * LDA + key0 + lr]);
            a[2] = __float_as_uint(Pw[lq * LDA + key0 + lr + 4]);
            a[3] = __float_as_uint(Pw[(lq + 8) * LDA + key0 + lr + 4]);
#pragma unroll
            for (int j = 0; j < 8; j++) {
                unsigned b[2];
                b[0] = __float_as_uint(Vs[(key0 + lr) * LDA + j * 8 + lq]);
                b[1] = __float_as_uint(Vs[(key0 + lr + 4) * LDA + j * 8 + lq]);
                mma8(o[j], a, b);
            }
        }
        __syncwarp();
    }

    const int bb = bh / Hh;
    const int h = bh % Hh;
    const float inv0 = 1.0f / l0;
    const float inv1 = 1.0f / l1;
    const int t0 = qbase + qr0 + lq;
    const int t1 = t0 + 8;
#pragma unroll
    for (int j = 0; j < 8; j++) {
        const int d = j * 8 + lr * 2;
        float2 w0 = make_float2(o[j][0] * inv0, o[j][1] * inv0);
        float2 w1 = make_float2(o[j][2] * inv1, o[j][3] * inv1);
        *(float2*)&g_y[((size_t)(bb * Tt + t0)) * Cc + h * Dd + d] = w0;
        *(float2*)&g_y[((size_t)(bb * Tt + t1)) * Cc + h * Dd + d] = w1;
    }
}

// =============================================================================
extern "C" void kernel_launch(void* const* d_in, const int* in_sizes, int n_in,
                              void* d_out, int out_size) {
    const float* x     = (const float*)d_in[0];
    const float* Wqkv  = (const float*)d_in[1];
    const float* bqkv  = (const float*)d_in[2];
    const float* Wproj = (const float*)d_in[3];
    const float* bproj = (const float*)d_in[4];
    float* out = (float*)d_out;

    (void)cudaFuncSetAttribute(gemm_tf32, cudaFuncAttributeMaxDynamicSharedMemorySize,
                               SM_GEMM_BYTES);

    // 1) QKV projection (tf32 mma, 128x256 tiles)
    dim3 g1(3 * Cc / 256, Bb * Tt / 128);   // (12, 32)
    gemm_tf32<<<g1, 256, SM_GEMM_BYTES>>>(x, Wqkv, bqkv, nullptr, 3 * Cc, 0);

    // 2) flash attention (tf32 mma)
    const size_t smem_bytes =
        (size_t)(128 * 68 + 64 * 68 + 64 * 68 + 8 * 16 * 68) * sizeof(float); // 104448
    (void)cudaFuncSetAttribute(attn_tf32, cudaFuncAttributeMaxDynamicSharedMemorySize,
                               (int)smem_bytes);
    attn_tf32<<<dim3(Tt / 128, Bb * Hh), 256, smem_bytes>>>();

    // 3) output projection (tf32 mma, 128x256 tiles)
    dim3 g3(Cc / 256, Bb * Tt / 128);       // (4, 32)
    gemm_tf32<<<g3, 256, SM_GEMM_BYTES>>>(nullptr, Wproj, bproj, out, Cc, 1);
}